// round 15
// baseline (speedup 1.0000x reference)
#include <cuda_runtime.h>
#include <math.h>

#define CIN  64
#define COUT 128
#define HH   512
#define WW   512

__device__ float  d_y[COUT * HH * WW];           // conv output          (128 MB)
__device__ float2 d_spec[(COUT / 2) * HH * WW];  // packed pair spectrum (128 MB)

// ===========================================================================
// Packed fp32x2 helpers (sm_103a dual-FMA path)
// ===========================================================================
__device__ __forceinline__ unsigned long long pack2(float a, float b) {
    unsigned long long r;
    asm("mov.b64 %0, {%1, %2};" : "=l"(r) : "f"(a), "f"(b));
    return r;
}
__device__ __forceinline__ void unpack2(unsigned long long v, float& a, float& b) {
    asm("mov.b64 {%0, %1}, %2;" : "=f"(a), "=f"(b) : "l"(v));
}
__device__ __forceinline__ void fma2(unsigned long long& acc,
                                     unsigned long long x, unsigned long long w) {
    asm("fma.rn.f32x2 %0, %1, %2, %0;" : "+l"(acc) : "l"(x), "l"(w));
}

// ===========================================================================
// Conv 3x3 (cross-correlation, same padding), packed fp32x2 FMA.
// Block: 8 co x 32 h x 64 w. Thread: 8 co x 8 w px (32 u64 accumulators).
// Smem-free x path: per kh row two LDG.128; w-halo via in-warp shfl
// (warp = 4 ty-rows x 8 tx), edge lanes patch with predicated scalar LDG.
// 36 LDS.128 weight broadcasts feed 288 FFMA2 per ci. Zero ci-loop barriers.
// ===========================================================================
#define CO_T 8
#define HT   32
#define WT   64

__global__ __launch_bounds__(256, 2) void conv3x3_kernel(
    const float* __restrict__ x, const float* __restrict__ wgt,
    const float* __restrict__ bias)
{
    __shared__ unsigned long long swd[CIN * 9 * CO_T];   // [ci][k][co], 36.9 KB

    const int tid = threadIdx.x;
    const int tx  = tid & 7;     // 8 groups along W, 8 px each
    const int ty  = tid >> 3;    // 32 rows
    const int w0  = blockIdx.x * WT;
    const int h0  = blockIdx.y * HT;
    const int co0 = blockIdx.z * CO_T;

    // ---- one-time weight preload: swd[(ci*9 + k)*8 + c] = dup(w[co0+c][ci][k])
    for (int i = tid; i < CIN * 9 * CO_T; i += 256) {
        int c   = i & 7;
        int kci = i >> 3;
        int ci  = kci / 9;
        int k   = kci - ci * 9;
        float w = wgt[((co0 + c) * CIN + ci) * 9 + k];
        swd[i] = pack2(w, w);
    }
    __syncthreads();     // the ONLY block barrier

    const int  h     = h0 + ty;                // output row
    const bool v0    = (h - 1 >= 0);
    const bool v2    = (h + 1 < HH);
    const bool lEdge = (tx == 0), lVal = (w0 > 0);
    const bool rEdge = (tx == 7), rVal = (w0 + WT < WW);

    const float* p0 = x + (h - 1) * WW + w0 + tx * 8;
    const float* p1 = x + (h    ) * WW + w0 + tx * 8;
    const float* p2 = x + (h + 1) * WW + w0 + tx * 8;

    unsigned long long acc[CO_T][4];
#pragma unroll
    for (int c = 0; c < CO_T; c++)
#pragma unroll
        for (int q = 0; q < 4; q++) acc[c][q] = 0ull;

    const unsigned long long* wci = swd;

    for (int ci = 0; ci < CIN; ci++) {
#pragma unroll
        for (int kh = 0; kh < 3; kh++) {
            const float* rp = (kh == 0) ? p0 : (kh == 1) ? p1 : p2;
            const bool   hv = (kh == 0) ? v0 : (kh == 1) ? true : v2;

            float4 a4 = hv ? *(const float4*)rp
                           : make_float4(0.f, 0.f, 0.f, 0.f);
            float4 b4 = hv ? *(const float4*)(rp + 4)
                           : make_float4(0.f, 0.f, 0.f, 0.f);
            float lft = __shfl_up_sync  (0xffffffffu, b4.w, 1);
            float rgt = __shfl_down_sync(0xffffffffu, a4.x, 1);
            if (lEdge) lft = (hv && lVal) ? rp[-1] : 0.f;
            if (rEdge) rgt = (hv && rVal) ? rp[8]  : 0.f;

            // packed pairs: O* = odd-shift pairs, E* = aligned pairs
            unsigned long long O0 = pack2(lft,  a4.x);
            unsigned long long E0 = pack2(a4.x, a4.y);
            unsigned long long O1 = pack2(a4.y, a4.z);
            unsigned long long E1 = pack2(a4.z, a4.w);
            unsigned long long O2 = pack2(a4.w, b4.x);
            unsigned long long E2 = pack2(b4.x, b4.y);
            unsigned long long O3 = pack2(b4.y, b4.z);
            unsigned long long E3 = pack2(b4.z, b4.w);
            unsigned long long O4 = pack2(b4.w, rgt);

            unsigned long long xq[3][4] = {
                { O0, O1, O2, O3 },    // kw = 0 (input px-1)
                { E0, E1, E2, E3 },    // kw = 1 (input px)
                { O1, O2, O3, O4 }     // kw = 2 (input px+1)
            };

#pragma unroll
            for (int kw = 0; kw < 3; kw++) {
                const unsigned long long* wk = wci + (kh * 3 + kw) * CO_T;
#pragma unroll
                for (int cp = 0; cp < CO_T; cp += 2) {
                    ulonglong2 w2 = *(const ulonglong2*)(wk + cp);   // LDS.128 bcast
#pragma unroll
                    for (int q = 0; q < 4; q++) {
                        fma2(acc[cp][q],     xq[kw][q], w2.x);
                        fma2(acc[cp + 1][q], xq[kw][q], w2.y);
                    }
                }
            }
        }
        p0 += HH * WW; p1 += HH * WW; p2 += HH * WW;
        wci += 9 * CO_T;
    }

#pragma unroll
    for (int c = 0; c < CO_T; c++) {
        float bv = bias[co0 + c];
        float q0, q1, q2, q3, q4, q5, q6, q7;
        unpack2(acc[c][0], q0, q1);
        unpack2(acc[c][1], q2, q3);
        unpack2(acc[c][2], q4, q5);
        unpack2(acc[c][3], q6, q7);
        float* orow = &d_y[((co0 + c) * HH + h) * WW + w0 + tx * 8];
        *(float4*)(orow)     = make_float4(q0 + bv, q1 + bv, q2 + bv, q3 + bv);
        *(float4*)(orow + 4) = make_float4(q4 + bv, q5 + bv, q6 + bv, q7 + bv);
    }
}

// ===========================================================================
// Register-resident 512-pt FFT (unchanged core)
// ===========================================================================
template<int INV>
__device__ __forceinline__ void fft16_reg(float2 v[16])
{
    float2 t;
    t = v[1];  v[1]  = v[8];  v[8]  = t;
    t = v[2];  v[2]  = v[4];  v[4]  = t;
    t = v[3];  v[3]  = v[12]; v[12] = t;
    t = v[5];  v[5]  = v[10]; v[10] = t;
    t = v[7];  v[7]  = v[14]; v[14] = t;
    t = v[11]; v[11] = v[13]; v[13] = t;

    const float CC[8] = { 1.f,  0.92387953251128674f,  0.70710678118654752f,
                          0.38268343236508977f, 0.f, -0.38268343236508977f,
                         -0.70710678118654752f, -0.92387953251128674f };
    const float SS[8] = { 0.f,  0.38268343236508977f,  0.70710678118654752f,
                          0.92387953251128674f, 1.f,  0.92387953251128674f,
                          0.70710678118654752f,  0.38268343236508977f };
#pragma unroll
    for (int st = 1; st <= 4; st++) {
        const int half = 1 << (st - 1);
#pragma unroll
        for (int j = 0; j < 8; j++) {
            const int pos = j & (half - 1);
            const int i0  = ((j >> (st - 1)) << st) | pos;
            const int i1  = i0 + half;
            const int tj  = pos << (4 - st);
            const float wr = CC[tj];
            const float wi = INV ? SS[tj] : -SS[tj];
            float br = v[i1].x * wr - v[i1].y * wi;
            float bi = v[i1].x * wi + v[i1].y * wr;
            v[i1].x = v[i0].x - br; v[i1].y = v[i0].y - bi;
            v[i0].x += br;          v[i0].y += bi;
        }
    }
}

template<int INV>
__device__ __forceinline__ void fft32_xlane(float2 v[16], int lane)
{
    const unsigned m = 0xffffffffu;
    int rl = __brev(lane) >> 27;
#pragma unroll
    for (int r = 0; r < 16; r++) {
        v[r].x = __shfl_sync(m, v[r].x, rl);
        v[r].y = __shfl_sync(m, v[r].y, rl);
    }
#pragma unroll
    for (int st = 1; st <= 5; st++) {
        const int half = 1 << (st - 1);
        float ang = (INV ? 3.14159265358979323f : -3.14159265358979323f)
                    * (float)(lane & (half - 1)) / (float)half;
        float wi, wr;
        __sincosf(ang, &wi, &wr);
        const float sgn = (lane & half) ? -1.f : 1.f;
        const bool hi = (lane & half) != 0;
#pragma unroll
        for (int r = 0; r < 16; r++) {
            float px = __shfl_xor_sync(m, v[r].x, half);
            float py = __shfl_xor_sync(m, v[r].y, half);
            float bx = hi ? v[r].x : px;
            float by = hi ? v[r].y : py;
            float ax = hi ? px : v[r].x;
            float ay = hi ? py : v[r].y;
            float tx = bx * wr - by * wi;
            float ty = bx * wi + by * wr;
            v[r].x = fmaf(sgn, tx, ax);
            v[r].y = fmaf(sgn, ty, ay);
        }
    }
}

template<int INV>
__device__ __forceinline__ void twiddle512(float2 v[16], int lane)
{
    float ang = (INV ? 6.28318530717958648f : -6.28318530717958648f)
                * (float)lane / 512.f;
    float s, c;
    __sincosf(ang, &s, &c);
    float wr = 1.f, wi = 0.f;
#pragma unroll
    for (int r = 1; r < 16; r++) {
        float nwr = wr * c - wi * s;
        float nwi = wr * s + wi * c;
        wr = nwr; wi = nwi;
        float xr = v[r].x, xi = v[r].y;
        v[r].x = xr * wr - xi * wi;
        v[r].y = xr * wi + xi * wr;
    }
}

__device__ __forceinline__ void fft512_fwd(float2 v[16], int lane)
{
    fft16_reg<0>(v);
    twiddle512<0>(v, lane);
    fft32_xlane<0>(v, lane);
}
__device__ __forceinline__ void fft512_inv(float2 v[16], int lane)
{
    fft32_xlane<1>(v, lane);
    twiddle512<1>(v, lane);
    fft16_reg<1>(v);
}

__device__ __forceinline__ int swz(int idx) { return idx ^ ((idx >> 7) & 15); }
__device__ __forceinline__ int padz(int i) { return i + (i >> 4); }
__device__ __forceinline__ int padm(int i) { return i + (i >> 5); }

// ===========================================================================
// Pass 1: column FFT of packed pair z = y[2p] + i*y[2p+1].
// ===========================================================================
__global__ __launch_bounds__(256) void fft_cols_fwd2()
{
    __shared__ char raw[36864];
    float2* sIn  = (float2*)raw;
    float2* sOut = (float2*)raw;

    const int tid  = threadIdx.x;
    const int lane = tid & 31;
    const int wp   = tid >> 5;
    const int p    = blockIdx.y;
    const int w0   = blockIdx.x * 8;

    const float* y1 = &d_y[(2 * p)     * HH * WW];
    const float* y2 = &d_y[(2 * p + 1) * HH * WW];
    for (int i = tid; i < 4096; i += 256) {
        int h = i >> 3, c = i & 7;
        int g = h * WW + w0 + c;
        sIn[h * 9 + c] = make_float2(y1[g], y2[g]);
    }
    __syncthreads();

    float2 v[16];
#pragma unroll
    for (int r = 0; r < 16; r++)
        v[r] = sIn[(lane + 32 * r) * 9 + wp];
    __syncthreads();

    fft512_fwd(v, lane);

#pragma unroll
    for (int r = 0; r < 16; r++) {
        int k = r + 16 * lane;
        sOut[swz((k << 3) | wp)] = v[r];
    }
    __syncthreads();

    for (int i = tid; i < 4096; i += 256) {
        int k = i >> 3, c = i & 7;
        d_spec[(p * HH + k) * WW + w0 + c] = sOut[swz(i)];
    }
}

// ===========================================================================
// Pass 2: Hermitian-split row pass (unchanged).
// ===========================================================================
__global__ __launch_bounds__(128) void fft_rows_mask2(const float* __restrict__ mask)
{
    __shared__ float2 zbuf[2][2][544];
    __shared__ float  mbuf[2][4][528];

    const int tid   = threadIdx.x;
    const int lane  = tid & 31;
    const int wp    = tid >> 5;
    const int slot  = wp >> 1;
    const int role  = wp & 1;
    const int p     = blockIdx.y;
    const int k1    = blockIdx.x * 2 + slot;
    const bool act  = (k1 <= 256);

    const int rowA  = k1;
    const int rowB  = (512 - k1) & 511;
    const int myrow = role ? rowB : rowA;

    float2 v[16];
    if (act) {
        const float2* srow = &d_spec[(p * HH + myrow) * WW];
#pragma unroll
        for (int r = 0; r < 16; r++)
            v[r] = srow[lane + 32 * r];

        const float* m1 = &mask[((2 * p)     * HH + myrow) * WW];
        const float* m2 = &mask[((2 * p + 1) * HH + myrow) * WW];
        float* d1 = mbuf[slot][role];
        float* d2 = mbuf[slot][2 + role];
#pragma unroll
        for (int t = 0; t < 16; t++) {
            int i = lane + 32 * t;
            d1[padm(i)] = m1[i];
            d2[padm(i)] = m2[i];
        }

        fft512_fwd(v, lane);

        float2* zme = zbuf[slot][role];
#pragma unroll
        for (int r = 0; r < 16; r++) {
            int k = r + 16 * lane;
            zme[padz(k)] = v[r];
        }
    }
    __syncthreads();

    if (act) {
        const float c4 = 0.25f / (512.0f * 512.0f);
        const float* m1A = mbuf[slot][0];
        const float* m1B = mbuf[slot][1];
        const float* m2A = mbuf[slot][2];
        const float* m2B = mbuf[slot][3];
        const float2* zA = zbuf[slot][0];
        const float2* zB = zbuf[slot][1];

#pragma unroll
        for (int r = 0; r < 16; r++) {
            int k  = r + 16 * lane;
            int r2 = (512 - k) & 511;
            if (role == 0) {
                float2 zb = zB[padz(r2)];
                float sx = v[r].x + zb.x, sy = v[r].y - zb.y;
                float dx = v[r].x - zb.x, dy = v[r].y + zb.y;
                float m1v = (m1A[padm(k)] + m1B[padm(r2)]) * c4;
                float m2v = (m2A[padm(k)] + m2B[padm(r2)]) * c4;
                v[r] = make_float2(m1v * sx + m2v * dx, m1v * sy + m2v * dy);
            } else {
                float2 za = zA[padz(r2)];
                float sx = za.x + v[r].x, sy = za.y - v[r].y;
                float dx = za.x - v[r].x, dy = za.y + v[r].y;
                float m1v = (m1A[padm(r2)] + m1B[padm(k)]) * c4;
                float m2v = (m2A[padm(r2)] + m2B[padm(k)]) * c4;
                v[r] = make_float2(m1v * sx - m2v * dx, -m1v * sy + m2v * dy);
            }
        }

        fft512_inv(v, lane);

        if (!(role == 1 && rowB == rowA)) {
            float2* orow = &d_spec[(p * HH + myrow) * WW];
#pragma unroll
            for (int r = 0; r < 16; r++)
                orow[lane + 32 * r] = v[r];
        }
    }
}

// ===========================================================================
// Pass 3: inverse column FFT; Re -> channel 2p, Im -> channel 2p+1.
// ===========================================================================
__global__ __launch_bounds__(256) void fft_cols_inv2(float* __restrict__ out)
{
    __shared__ char raw[36864];
    float2* sIn  = (float2*)raw;
    float2* sOut = (float2*)raw;

    const int tid  = threadIdx.x;
    const int lane = tid & 31;
    const int wp   = tid >> 5;
    const int p    = blockIdx.y;
    const int w0   = blockIdx.x * 8;

    for (int i = tid; i < 4096; i += 256) {
        int k = i >> 3, c = i & 7;
        sIn[swz(i)] = d_spec[(p * HH + k) * WW + w0 + c];
    }
    __syncthreads();

    float2 v[16];
#pragma unroll
    for (int r = 0; r < 16; r++) {
        int k = r + 16 * lane;
        v[r] = sIn[swz((k << 3) | wp)];
    }
    __syncthreads();

    fft512_inv(v, lane);

#pragma unroll
    for (int r = 0; r < 16; r++)
        sOut[(lane + 32 * r) * 9 + wp] = v[r];
    __syncthreads();

    float* o1 = &out[(2 * p)     * HH * WW];
    float* o2 = &out[(2 * p + 1) * HH * WW];
    for (int i = tid; i < 4096; i += 256) {
        int hh = i >> 3, c = i & 7;
        float2 s = sOut[hh * 9 + c];
        int g = hh * WW + w0 + c;
        o1[g] = s.x;
        o2[g] = s.y;
    }
}

// ===========================================================================
extern "C" void kernel_launch(void* const* d_in, const int* in_sizes, int n_in,
                              void* d_out, int out_size)
{
    const float* x    = (const float*)d_in[0];   // (64,512,512)
    const float* wgt  = (const float*)d_in[1];   // (128,64,3,3)
    const float* bias = (const float*)d_in[2];   // (128,)
    const float* mask = (const float*)d_in[3];   // (128,512,512)
    float* out = (float*)d_out;                  // (128,512,512)

    conv3x3_kernel<<<dim3(WW / WT, HH / HT, COUT / CO_T), 256>>>(x, wgt, bias);
    fft_cols_fwd2 <<<dim3(WW / 8, COUT / 2), 256>>>();
    fft_rows_mask2<<<dim3(129, COUT / 2), 128>>>(mask);
    fft_cols_inv2 <<<dim3(WW / 8, COUT / 2), 256>>>(out);
}

// round 17
// speedup vs baseline: 1.0232x; 1.0232x over previous
#include <cuda_runtime.h>
#include <cuda_bf16.h>
#include <math.h>
#include <stdint.h>

#define CIN  64
#define COUT 128
#define HH   512
#define WW   512

__device__ float  d_y[COUT * HH * WW];           // conv output          (128 MB)
__device__ float2 d_spec[(COUT / 2) * HH * WW];  // packed pair spectrum (128 MB)

// channels-last split input, K-extended: [h][w][k], k-pitch 200 (192 used + pad)
// per ci: k=3ci:x_hi, 3ci+1:x_hi, 3ci+2:x_lo
__device__ __align__(16) __nv_bfloat16 d_xe[HH * WW * 200];   // 105 MB
// weights: [p=kh*3+kw][co][k=192]; per ci: 3ci:w_hi, 3ci+1:w_lo, 3ci+2:w_hi
__device__ __align__(16) __nv_bfloat16 d_we[9 * COUT * 192];  // 442 KB

// ===========================================================================
// Prep 1: x (ci,h,w) f32 -> d_xe channels-last K-extended bf16
// ===========================================================================
__global__ __launch_bounds__(256) void xe_kernel(const float* __restrict__ x)
{
    __shared__ float tile[64][33];
    const int h  = blockIdx.y;
    const int wb = blockIdx.x;          // 16 blocks of 32 w
    const int tid = threadIdx.x;

    const int ciB = tid >> 5, w = tid & 31;
#pragma unroll
    for (int c8 = 0; c8 < 8; c8++) {
        int ci = c8 * 8 + ciB;
        tile[ci][w] = x[(ci * HH + h) * WW + wb * 32 + w];
    }
    __syncthreads();

    const int ww = tid >> 3, cj = tid & 7;   // ww 0..31, cj 0..7 (8 ci each)
    unsigned short bs[24];
#pragma unroll
    for (int e = 0; e < 8; e++) {
        float v = tile[cj * 8 + e][ww];
        __nv_bfloat16 hi = __float2bfloat16(v);
        __nv_bfloat16 lo = __float2bfloat16(v - __bfloat162float(hi));
        unsigned short hs = __bfloat16_as_ushort(hi);
        unsigned short ls = __bfloat16_as_ushort(lo);
        bs[3 * e]     = hs;
        bs[3 * e + 1] = hs;
        bs[3 * e + 2] = ls;
    }
    uint32_t w32[12];
#pragma unroll
    for (int i = 0; i < 12; i++)
        w32[i] = (uint32_t)bs[2 * i] | ((uint32_t)bs[2 * i + 1] << 16);

    __nv_bfloat16* dst = d_xe + (h * WW + wb * 32 + ww) * 200 + cj * 24;
    uint4* d4 = (uint4*)dst;                      // 48B-aligned
    d4[0] = make_uint4(w32[0], w32[1], w32[2],  w32[3]);
    d4[1] = make_uint4(w32[4], w32[5], w32[6],  w32[7]);
    d4[2] = make_uint4(w32[8], w32[9], w32[10], w32[11]);
    if (cj == 7)                                   // zero pad k = 192..199
        *(uint4*)(d_xe + (h * WW + wb * 32 + ww) * 200 + 192)
            = make_uint4(0u, 0u, 0u, 0u);
}

// ===========================================================================
// Prep 2: weights -> d_we [p][co][192]
// ===========================================================================
__global__ __launch_bounds__(256) void we_kernel(const float* __restrict__ wgt)
{
    int idx = blockIdx.x * 256 + threadIdx.x;     // 9*128*64 = 73728
    if (idx >= 9 * COUT * CIN) return;
    int p  = idx / (COUT * CIN);
    int r  = idx - p * (COUT * CIN);
    int co = r >> 6, ci = r & 63;
    float v = wgt[(co * CIN + ci) * 9 + p];
    __nv_bfloat16 hi = __float2bfloat16(v);
    __nv_bfloat16 lo = __float2bfloat16(v - __bfloat162float(hi));
    __nv_bfloat16* dst = d_we + (p * COUT + co) * 192 + 3 * ci;
    dst[0] = hi; dst[1] = lo; dst[2] = hi;
}

// ===========================================================================
// Conv 3x3 as mma.sync (HMMA) implicit GEMM.
// CTA: 128 co x 1 h x 64 w. 8 warps = 4 co-groups (m32) x 2 n-groups (n32).
// smem: 3 kh-slabs of [66 w][200 k] bf16 = 79200 B (dynamic).
// K-loop: 9 (kh,kw) x 12 k16-steps; kw = +-1 w-row offset in slab.
// ===========================================================================
#define SLABW 66
#define KP    200
#define SLAB  (SLABW * KP)
#define CV_SMEM (3 * SLAB * 2)

__device__ __forceinline__ void mma16816(float* d, const uint32_t* a,
                                         uint32_t b0, uint32_t b1)
{
    asm volatile(
        "mma.sync.aligned.m16n8k16.row.col.f32.bf16.bf16.f32 "
        "{%0,%1,%2,%3}, {%4,%5,%6,%7}, {%8,%9}, {%0,%1,%2,%3};"
        : "+f"(d[0]), "+f"(d[1]), "+f"(d[2]), "+f"(d[3])
        : "r"(a[0]), "r"(a[1]), "r"(a[2]), "r"(a[3]), "r"(b0), "r"(b1));
}

__global__ __launch_bounds__(256) void conv_mma(const float* __restrict__ bias)
{
    extern __shared__ __nv_bfloat16 sxe[];       // 3 * SLAB halfs
    const int tid  = threadIdx.x;
    const int lane = tid & 31;
    const int wid  = tid >> 5;
    const int w0   = blockIdx.x * 64;
    const int h    = blockIdx.y;

    // ---- stage 3 kh-slabs: flat uint4 copies, zero out-of-range rows ----
    {
        uint4* s4 = (uint4*)sxe;
        const int CH = KP / 8;                   // 25 uint4 per w-row
        for (int c = tid; c < 3 * SLABW * CH; c += 256) {
            int kh = c / (SLABW * CH);
            int r  = c - kh * (SLABW * CH);
            int ws = r / CH, q = r - ws * CH;
            int hg = h + kh - 1, wg = w0 - 1 + ws;
            uint4 v = make_uint4(0u, 0u, 0u, 0u);
            if (hg >= 0 && hg < HH && wg >= 0 && wg < WW)
                v = ((const uint4*)(d_xe + (hg * WW + wg) * KP))[q];
            s4[(kh * SLABW + ws) * CH + q] = v;
        }
    }
    __syncthreads();

    const int cog = wid & 3;       // co group: 32 co each
    const int ng  = wid >> 2;      // n group: 32 w each
    const int g   = lane >> 2;     // groupID (0..7)
    const int tg  = lane & 3;      // thread-in-group

    float acc[2][4][4];
#pragma unroll
    for (int mf = 0; mf < 2; mf++)
#pragma unroll
        for (int nf = 0; nf < 4; nf++)
#pragma unroll
            for (int q = 0; q < 4; q++) acc[mf][nf][q] = 0.f;

#pragma unroll 1
    for (int p = 0; p < 9; p++) {
        const int kh = p / 3, kw = p - kh * 3;
        const __nv_bfloat16* slab = sxe + kh * SLAB;
        const __nv_bfloat16* wp   = d_we + (p * COUT + cog * 32) * 192;

#pragma unroll
        for (int ks = 0; ks < 12; ks++) {
            const int k0 = ks * 16;
            uint32_t a[2][4];
#pragma unroll
            for (int mf = 0; mf < 2; mf++) {
                const __nv_bfloat16* wc = wp + (mf * 16 + g) * 192 + k0 + tg * 2;
                a[mf][0] = *(const uint32_t*)(wc);
                a[mf][1] = *(const uint32_t*)(wc + 8 * 192);
                a[mf][2] = *(const uint32_t*)(wc + 8);
                a[mf][3] = *(const uint32_t*)(wc + 8 * 192 + 8);
            }
#pragma unroll
            for (int nf = 0; nf < 4; nf++) {
                const __nv_bfloat16* bp =
                    slab + (ng * 32 + nf * 8 + g + kw) * KP + k0 + tg * 2;
                uint32_t b0 = *(const uint32_t*)(bp);
                uint32_t b1 = *(const uint32_t*)(bp + 8);
                mma16816(acc[0][nf], a[0], b0, b1);
                mma16816(acc[1][nf], a[1], b0, b1);
            }
        }
    }

    // ---- epilogue: frags -> d_y rows (+bias) ----
#pragma unroll
    for (int mf = 0; mf < 2; mf++) {
        const int co = cog * 32 + mf * 16 + g;
        const float bv0 = bias[co];
        const float bv1 = bias[co + 8];
#pragma unroll
        for (int nf = 0; nf < 4; nf++) {
            const int w = w0 + ng * 32 + nf * 8 + tg * 2;
            float* y0 = &d_y[(co * HH + h) * WW + w];
            float* y1 = &d_y[((co + 8) * HH + h) * WW + w];
            *(float2*)y0 = make_float2(acc[mf][nf][0] + bv0,
                                       acc[mf][nf][1] + bv0);
            *(float2*)y1 = make_float2(acc[mf][nf][2] + bv1,
                                       acc[mf][nf][3] + bv1);
        }
    }
}

// ===========================================================================
// Register-resident 512-pt FFT (unchanged, round-14 best)
// ===========================================================================
template<int INV>
__device__ __forceinline__ void fft16_reg(float2 v[16])
{
    float2 t;
    t = v[1];  v[1]  = v[8];  v[8]  = t;
    t = v[2];  v[2]  = v[4];  v[4]  = t;
    t = v[3];  v[3]  = v[12]; v[12] = t;
    t = v[5];  v[5]  = v[10]; v[10] = t;
    t = v[7];  v[7]  = v[14]; v[14] = t;
    t = v[11]; v[11] = v[13]; v[13] = t;

    const float CC[8] = { 1.f,  0.92387953251128674f,  0.70710678118654752f,
                          0.38268343236508977f, 0.f, -0.38268343236508977f,
                         -0.70710678118654752f, -0.92387953251128674f };
    const float SS[8] = { 0.f,  0.38268343236508977f,  0.70710678118654752f,
                          0.92387953251128674f, 1.f,  0.92387953251128674f,
                          0.70710678118654752f,  0.38268343236508977f };
#pragma unroll
    for (int st = 1; st <= 4; st++) {
        const int half = 1 << (st - 1);
#pragma unroll
        for (int j = 0; j < 8; j++) {
            const int pos = j & (half - 1);
            const int i0  = ((j >> (st - 1)) << st) | pos;
            const int i1  = i0 + half;
            const int tj  = pos << (4 - st);
            const float wr = CC[tj];
            const float wi = INV ? SS[tj] : -SS[tj];
            float br = v[i1].x * wr - v[i1].y * wi;
            float bi = v[i1].x * wi + v[i1].y * wr;
            v[i1].x = v[i0].x - br; v[i1].y = v[i0].y - bi;
            v[i0].x += br;          v[i0].y += bi;
        }
    }
}

template<int INV>
__device__ __forceinline__ void fft32_xlane(float2 v[16], int lane)
{
    const unsigned m = 0xffffffffu;
    int rl = __brev(lane) >> 27;
#pragma unroll
    for (int r = 0; r < 16; r++) {
        v[r].x = __shfl_sync(m, v[r].x, rl);
        v[r].y = __shfl_sync(m, v[r].y, rl);
    }
#pragma unroll
    for (int st = 1; st <= 5; st++) {
        const int half = 1 << (st - 1);
        float ang = (INV ? 3.14159265358979323f : -3.14159265358979323f)
                    * (float)(lane & (half - 1)) / (float)half;
        float wi, wr;
        __sincosf(ang, &wi, &wr);
        const float sgn = (lane & half) ? -1.f : 1.f;
        const bool hi = (lane & half) != 0;
#pragma unroll
        for (int r = 0; r < 16; r++) {
            float px = __shfl_xor_sync(m, v[r].x, half);
            float py = __shfl_xor_sync(m, v[r].y, half);
            float bx = hi ? v[r].x : px;
            float by = hi ? v[r].y : py;
            float ax = hi ? px : v[r].x;
            float ay = hi ? py : v[r].y;
            float tx = bx * wr - by * wi;
            float ty = bx * wi + by * wr;
            v[r].x = fmaf(sgn, tx, ax);
            v[r].y = fmaf(sgn, ty, ay);
        }
    }
}

template<int INV>
__device__ __forceinline__ void twiddle512(float2 v[16], int lane)
{
    float ang = (INV ? 6.28318530717958648f : -6.28318530717958648f)
                * (float)lane / 512.f;
    float s, c;
    __sincosf(ang, &s, &c);
    float wr = 1.f, wi = 0.f;
#pragma unroll
    for (int r = 1; r < 16; r++) {
        float nwr = wr * c - wi * s;
        float nwi = wr * s + wi * c;
        wr = nwr; wi = nwi;
        float xr = v[r].x, xi = v[r].y;
        v[r].x = xr * wr - xi * wi;
        v[r].y = xr * wi + xi * wr;
    }
}

__device__ __forceinline__ void fft512_fwd(float2 v[16], int lane)
{
    fft16_reg<0>(v);
    twiddle512<0>(v, lane);
    fft32_xlane<0>(v, lane);
}
__device__ __forceinline__ void fft512_inv(float2 v[16], int lane)
{
    fft32_xlane<1>(v, lane);
    twiddle512<1>(v, lane);
    fft16_reg<1>(v);
}

__device__ __forceinline__ int swz(int idx)  { return idx ^ ((idx >> 7) & 15); }
__device__ __forceinline__ int padz(int i)   { return i + (i >> 4); }
__device__ __forceinline__ int padm(int i)   { return i + (i >> 5); }

// ===========================================================================
// Pass 1: column FFT of packed pair z = y[2p] + i*y[2p+1].
// ===========================================================================
__global__ __launch_bounds__(256) void fft_cols_fwd2()
{
    __shared__ char raw[36864];
    float2* sIn  = (float2*)raw;
    float2* sOut = (float2*)raw;

    const int tid  = threadIdx.x;
    const int lane = tid & 31;
    const int wp   = tid >> 5;
    const int p    = blockIdx.y;
    const int w0   = blockIdx.x * 8;

    const float* y1 = &d_y[(2 * p)     * HH * WW];
    const float* y2 = &d_y[(2 * p + 1) * HH * WW];
    for (int i = tid; i < 4096; i += 256) {
        int h = i >> 3, c = i & 7;
        int g = h * WW + w0 + c;
        sIn[h * 9 + c] = make_float2(y1[g], y2[g]);
    }
    __syncthreads();

    float2 v[16];
#pragma unroll
    for (int r = 0; r < 16; r++)
        v[r] = sIn[(lane + 32 * r) * 9 + wp];
    __syncthreads();

    fft512_fwd(v, lane);

#pragma unroll
    for (int r = 0; r < 16; r++) {
        int k = r + 16 * lane;
        sOut[swz((k << 3) | wp)] = v[r];
    }
    __syncthreads();

    for (int i = tid; i < 4096; i += 256) {
        int k = i >> 3, c = i & 7;
        d_spec[(p * HH + k) * WW + w0 + c] = sOut[swz(i)];
    }
}

// ===========================================================================
// Pass 2: Hermitian-split row pass (unchanged).
// ===========================================================================
__global__ __launch_bounds__(128) void fft_rows_mask2(const float* __restrict__ mask)
{
    __shared__ float2 zbuf[2][2][544];
    __shared__ float  mbuf[2][4][528];

    const int tid   = threadIdx.x;
    const int lane  = tid & 31;
    const int wp    = tid >> 5;
    const int slot  = wp >> 1;
    const int role  = wp & 1;
    const int p     = blockIdx.y;
    const int k1    = blockIdx.x * 2 + slot;
    const bool act  = (k1 <= 256);

    const int rowA  = k1;
    const int rowB  = (512 - k1) & 511;
    const int myrow = role ? rowB : rowA;

    float2 v[16];
    if (act) {
        const float2* srow = &d_spec[(p * HH + myrow) * WW];
#pragma unroll
        for (int r = 0; r < 16; r++)
            v[r] = srow[lane + 32 * r];

        const float* m1 = &mask[((2 * p)     * HH + myrow) * WW];
        const float* m2 = &mask[((2 * p + 1) * HH + myrow) * WW];
        float* d1 = mbuf[slot][role];
        float* d2 = mbuf[slot][2 + role];
#pragma unroll
        for (int t = 0; t < 16; t++) {
            int i = lane + 32 * t;
            d1[padm(i)] = m1[i];
            d2[padm(i)] = m2[i];
        }

        fft512_fwd(v, lane);

        float2* zme = zbuf[slot][role];
#pragma unroll
        for (int r = 0; r < 16; r++) {
            int k = r + 16 * lane;
            zme[padz(k)] = v[r];
        }
    }
    __syncthreads();

    if (act) {
        const float c4 = 0.25f / (512.0f * 512.0f);
        const float* m1A = mbuf[slot][0];
        const float* m1B = mbuf[slot][1];
        const float* m2A = mbuf[slot][2];
        const float* m2B = mbuf[slot][3];
        const float2* zA = zbuf[slot][0];
        const float2* zB = zbuf[slot][1];

#pragma unroll
        for (int r = 0; r < 16; r++) {
            int k  = r + 16 * lane;
            int r2 = (512 - k) & 511;
            if (role == 0) {
                float2 zb = zB[padz(r2)];
                float sx = v[r].x + zb.x, sy = v[r].y - zb.y;
                float dx = v[r].x - zb.x, dy = v[r].y + zb.y;
                float m1v = (m1A[padm(k)] + m1B[padm(r2)]) * c4;
                float m2v = (m2A[padm(k)] + m2B[padm(r2)]) * c4;
                v[r] = make_float2(m1v * sx + m2v * dx, m1v * sy + m2v * dy);
            } else {
                float2 za = zA[padz(r2)];
                float sx = za.x + v[r].x, sy = za.y - v[r].y;
                float dx = za.x - v[r].x, dy = za.y + v[r].y;
                float m1v = (m1A[padm(r2)] + m1B[padm(k)]) * c4;
                float m2v = (m2A[padm(r2)] + m2B[padm(k)]) * c4;
                v[r] = make_float2(m1v * sx - m2v * dx, -m1v * sy + m2v * dy);
            }
        }

        fft512_inv(v, lane);

        if (!(role == 1 && rowB == rowA)) {
            float2* orow = &d_spec[(p * HH + myrow) * WW];
#pragma unroll
            for (int r = 0; r < 16; r++)
                orow[lane + 32 * r] = v[r];
        }
    }
}

// ===========================================================================
// Pass 3: inverse column FFT; Re -> channel 2p, Im -> channel 2p+1.
// ===========================================================================
__global__ __launch_bounds__(256) void fft_cols_inv2(float* __restrict__ out)
{
    __shared__ char raw[36864];
    float2* sIn  = (float2*)raw;
    float2* sOut = (float2*)raw;

    const int tid  = threadIdx.x;
    const int lane = tid & 31;
    const int wp   = tid >> 5;
    const int p    = blockIdx.y;
    const int w0   = blockIdx.x * 8;

    for (int i = tid; i < 4096; i += 256) {
        int k = i >> 3, c = i & 7;
        sIn[swz(i)] = d_spec[(p * HH + k) * WW + w0 + c];
    }
    __syncthreads();

    float2 v[16];
#pragma unroll
    for (int r = 0; r < 16; r++) {
        int k = r + 16 * lane;
        v[r] = sIn[swz((k << 3) | wp)];
    }
    __syncthreads();

    fft512_inv(v, lane);

#pragma unroll
    for (int r = 0; r < 16; r++)
        sOut[(lane + 32 * r) * 9 + wp] = v[r];
    __syncthreads();

    float* o1 = &out[(2 * p)     * HH * WW];
    float* o2 = &out[(2 * p + 1) * HH * WW];
    for (int i = tid; i < 4096; i += 256) {
        int hh = i >> 3, c = i & 7;
        float2 s = sOut[hh * 9 + c];
        int g = hh * WW + w0 + c;
        o1[g] = s.x;
        o2[g] = s.y;
    }
}

// ===========================================================================
extern "C" void kernel_launch(void* const* d_in, const int* in_sizes, int n_in,
                              void* d_out, int out_size)
{
    const float* x    = (const float*)d_in[0];   // (64,512,512)
    const float* wgt  = (const float*)d_in[1];   // (128,64,3,3)
    const float* bias = (const float*)d_in[2];   // (128,)
    const float* mask = (const float*)d_in[3];   // (128,512,512)
    float* out = (float*)d_out;                  // (128,512,512)

    cudaFuncSetAttribute(conv_mma,
                         cudaFuncAttributeMaxDynamicSharedMemorySize, CV_SMEM);

    xe_kernel<<<dim3(16, HH), 256>>>(x);
    we_kernel<<<288, 256>>>(wgt);
    conv_mma<<<dim3(8, HH), 256, CV_SMEM>>>(bias);
    fft_cols_fwd2 <<<dim3(WW / 8, COUT / 2), 256>>>();
    fft_rows_mask2<<<dim3(129, COUT / 2), 128>>>(mask);
    fft_cols_inv2 <<<dim3(WW / 8, COUT / 2), 256>>>(out);
}